// round 10
// baseline (speedup 1.0000x reference)
#include <cuda_runtime.h>
#include <cstdint>

#define NUM_TOKENS 8192
#define HIDDEN 4096
#define NUM_EXPERTS 8
#define INTER 2048
#define GU_COLS 4096
#define MAX_TILES 72

// ---------------- scratch ----------------
__device__ int g_counts[NUM_EXPERTS];
__device__ int g_lists[NUM_EXPERTS][NUM_TOKENS];
__device__ int g_is64;
// fragment-packed activations: [tile][kfrag][mfrag 8][128 floats]
__device__ float g_xpack[(size_t)MAX_TILES * (HIDDEN / 8) * 8 * 128];
__device__ float g_interp[(size_t)MAX_TILES * (INTER / 8) * 8 * 128];

// ---------------- helpers ----------------
__device__ __forceinline__ uint32_t f2tf(float f) {
    uint32_t r;
    asm("cvt.rna.tf32.f32 %0, %1;" : "=r"(r) : "f"(f));
    return r;
}
__device__ __forceinline__ float4 cvt4(float4 v) {
    float4 r;
    r.x = __uint_as_float(f2tf(v.x));
    r.y = __uint_as_float(f2tf(v.y));
    r.z = __uint_as_float(f2tf(v.z));
    r.w = __uint_as_float(f2tf(v.w));
    return r;
}
__device__ __forceinline__ void mma8(float* d, const uint32_t* a, uint32_t b0, uint32_t b1) {
    asm volatile(
        "mma.sync.aligned.m16n8k8.row.col.f32.tf32.tf32.f32 "
        "{%0,%1,%2,%3},{%4,%5,%6,%7},{%8,%9},{%0,%1,%2,%3};"
        : "+f"(d[0]), "+f"(d[1]), "+f"(d[2]), "+f"(d[3])
        : "r"(a[0]), "r"(a[1]), "r"(a[2]), "r"(a[3]), "r"(b0), "r"(b1));
}
__device__ __forceinline__ float silu(float g) { return g / (1.0f + __expf(-g)); }

__device__ __forceinline__ int find_tile(int t, int* e_out, int* m0_out, int* cnt_out) {
    int acc = 0;
#pragma unroll
    for (int e = 0; e < NUM_EXPERTS; e++) {
        int c = g_counts[e];
        int nt = (c + 127) >> 7;
        if (t < acc + nt) { *e_out = e; *m0_out = (t - acc) << 7; *cnt_out = c; return 1; }
        acc += nt;
    }
    return 0;
}

// ---------------- routing ----------------
__global__ void detect_kernel(const int* __restrict__ t32) {
    if (threadIdx.x == 0) {
        int all_zero = 1;
        for (int i = 0; i < 256; i++) {
            int idx = 2 * (i * (NUM_TOKENS / 256)) + 1;
            if (t32[idx] != 0) { all_zero = 0; break; }
        }
        g_is64 = all_zero;
    }
    if (threadIdx.x < NUM_EXPERTS) g_counts[threadIdx.x] = 0;
}

__global__ void route_kernel(const int* __restrict__ t32) {
    int i = blockIdx.x * blockDim.x + threadIdx.x;
    if (i < NUM_TOKENS) {
        int v = g_is64 ? t32[2 * i] : t32[i];
        int e = v & 7;
        int p = atomicAdd(&g_counts[e], 1);
        g_lists[e][p] = i;
    }
}

// ---------------- pack_x: gather routed tokens -> tf32 fragment layout ----------------
#define PX_PITCH 132
#define PX_SMEM (128 * PX_PITCH * 4 + 512)
__global__ __launch_bounds__(256) void pack_x_kernel(const float* __restrict__ x) {
    extern __shared__ char smem[];
    int e, m0, count;
    if (!find_tile(blockIdx.y, &e, &m0, &count)) return;
    const int kb = blockIdx.x;
    const int tid = threadIdx.x;
    int* tokS = (int*)smem;
    float* tile = (float*)(smem + 512);
    if (tid < 128) tokS[tid] = (m0 + tid < count) ? g_lists[e][m0 + tid] : -1;
    __syncthreads();
#pragma unroll
    for (int j = 0; j < 16; j++) {
        int idx = tid + j * 256;
        int r = idx >> 5, c4 = (idx & 31) * 4;
        int t = tokS[r];
        float4 v = make_float4(0.f, 0.f, 0.f, 0.f);
        if (t >= 0) v = *(const float4*)(x + (size_t)t * HIDDEN + kb * 128 + c4);
        *(float4*)(tile + r * PX_PITCH + c4) = cvt4(v);
    }
    __syncthreads();
    const int lane = tid & 31, w = tid >> 5;
    const int g = lane >> 2, tq = lane & 3;
#pragma unroll
    for (int i = 0; i < 16; i++) {
        int f = w * 16 + i;
        int mf = f & 7, kfl = f >> 3;
        const float* src = tile + (mf * 16 + g) * PX_PITCH + kfl * 8 + tq;
        float4 o;
        o.x = src[0];
        o.y = src[8 * PX_PITCH];
        o.z = src[4];
        o.w = src[8 * PX_PITCH + 4];
        size_t off = (((size_t)blockIdx.y * (HIDDEN / 8) + kb * 16 + kfl) * 8 + mf) * 128 + lane * 4;
        *(float4*)(g_xpack + off) = o;
    }
}

// ---------------- GEMM1: Xpack @ GU -> silu(gate)*up -> g_interp (packed) ----------------
// Barrier-free: A via LDG.128 from packed gmem, B via LDG.32+cvt from raw weights.
// grid: x = tile (m), y = n-tile  (consecutive CTAs share the B stream)
__global__ __launch_bounds__(256, 2) void gemm1_tc(const float* __restrict__ gup) {
    int e, m0, count;
    if (!find_tile(blockIdx.x, &e, &m0, &count)) return;
    const int t_id = blockIdx.x;
    const int n0 = blockIdx.y * 64;

    const int tid = threadIdx.x;
    const int wid = tid >> 5, lane = tid & 31;
    const int mw = wid >> 2, nw = wid & 3;
    const int g = lane >> 2, tq = lane & 3;

    // per-lane base pointers
    const float* ap = g_xpack + (size_t)t_id * (HIDDEN / 8) * 1024 + (mw * 4) * 128 + lane * 4;
    const float* bp = gup + (size_t)e * HIDDEN * GU_COLS
                          + (size_t)tq * GU_COLS + n0 + nw * 16 + g;

    float accg[4][2][4] = {};
    float accu[4][2][4] = {};

    const int NK = HIDDEN / 32;
    for (int kc = 0; kc < NK; kc++) {
#pragma unroll
        for (int kk = 0; kk < 4; kk++) {
            uint32_t bg[2][2], bu[2][2];
#pragma unroll
            for (int ni = 0; ni < 2; ni++) {
                const float* b0p = bp + kk * (8 * GU_COLS) + ni * 8;
                bg[ni][0] = f2tf(b0p[0]);
                bg[ni][1] = f2tf(b0p[4 * GU_COLS]);
                bu[ni][0] = f2tf(b0p[INTER]);
                bu[ni][1] = f2tf(b0p[4 * GU_COLS + INTER]);
            }
#pragma unroll
            for (int mi = 0; mi < 4; mi++) {
                const float4 av = *(const float4*)(ap + kk * 1024 + mi * 128);
                uint32_t a[4];
                a[0] = __float_as_uint(av.x);
                a[1] = __float_as_uint(av.y);
                a[2] = __float_as_uint(av.z);
                a[3] = __float_as_uint(av.w);
                mma8(accg[mi][0], a, bg[0][0], bg[0][1]);
                mma8(accg[mi][1], a, bg[1][0], bg[1][1]);
                mma8(accu[mi][0], a, bu[0][0], bu[0][1]);
                mma8(accu[mi][1], a, bu[1][0], bu[1][1]);
            }
        }
        ap += 4096;
        bp += 32 * GU_COLS;
    }

    // fused epilogue -> fragment-packed g_interp (tf32-rounded). Padded rows are
    // zeros in g_xpack -> acc 0 -> writes 0; gemm2 output scatter guards tokens.
#pragma unroll
    for (int mi = 0; mi < 4; mi++) {
        int mf = mw * 4 + mi;
#pragma unroll
        for (int ni = 0; ni < 2; ni++) {
            int c = nw * 16 + ni * 8 + 2 * tq;
            int kf = (n0 + c) >> 3;
            int hc2 = ((c >> 2) & 1) * 2;
            int tq0 = c & 3;
            float* base = g_interp + (((size_t)t_id * (INTER / 8) + kf) * 8 + mf) * 128;
            base[(g * 4 + tq0) * 4 + hc2] =
                __uint_as_float(f2tf(silu(accg[mi][ni][0]) * accu[mi][ni][0]));
            base[(g * 4 + tq0 + 1) * 4 + hc2] =
                __uint_as_float(f2tf(silu(accg[mi][ni][1]) * accu[mi][ni][1]));
            base[(g * 4 + tq0) * 4 + 1 + hc2] =
                __uint_as_float(f2tf(silu(accg[mi][ni][2]) * accu[mi][ni][2]));
            base[(g * 4 + tq0 + 1) * 4 + 1 + hc2] =
                __uint_as_float(f2tf(silu(accg[mi][ni][3]) * accu[mi][ni][3]));
        }
    }
}

// ---------------- GEMM2: g_interp @ down -> out (BN=128, barrier-free mainloop) ----------------
__global__ __launch_bounds__(256, 2) void gemm2_tc(const float* __restrict__ down,
                                                   float* __restrict__ out) {
    __shared__ int tokS[128];
    int e, m0, count;
    if (!find_tile(blockIdx.x, &e, &m0, &count)) return;
    const int t_id = blockIdx.x;
    const int n0 = blockIdx.y * 128;

    const int tid = threadIdx.x;
    const int wid = tid >> 5, lane = tid & 31;
    const int mw = wid >> 2, nw = wid & 3;
    const int g = lane >> 2, tq = lane & 3;

    if (tid < 128) tokS[tid] = (m0 + tid < count) ? g_lists[e][m0 + tid] : -1;
    __syncthreads();

    const float* ap = g_interp + (size_t)t_id * (INTER / 8) * 1024 + (mw * 4) * 128 + lane * 4;
    const float* bp = down + (size_t)e * INTER * HIDDEN
                           + (size_t)tq * HIDDEN + n0 + nw * 32 + g;

    float acc[4][4][4] = {};

    const int NK = INTER / 32;
    for (int kc = 0; kc < NK; kc++) {
#pragma unroll
        for (int kk = 0; kk < 4; kk++) {
            uint32_t bb[4][2];
#pragma unroll
            for (int ni = 0; ni < 4; ni++) {
                const float* b0p = bp + kk * (8 * HIDDEN) + ni * 8;
                bb[ni][0] = f2tf(b0p[0]);
                bb[ni][1] = f2tf(b0p[4 * HIDDEN]);
            }
#pragma unroll
            for (int mi = 0; mi < 4; mi++) {
                const float4 av = *(const float4*)(ap + kk * 1024 + mi * 128);
                uint32_t a[4];
                a[0] = __float_as_uint(av.x);
                a[1] = __float_as_uint(av.y);
                a[2] = __float_as_uint(av.z);
                a[3] = __float_as_uint(av.w);
#pragma unroll
                for (int ni = 0; ni < 4; ni++)
                    mma8(acc[mi][ni], a, bb[ni][0], bb[ni][1]);
            }
        }
        ap += 4096;
        bp += 32 * HIDDEN;
    }

#pragma unroll
    for (int mi = 0; mi < 4; mi++) {
        int r0 = mw * 64 + mi * 16 + g;
        int t0 = tokS[r0], t1 = tokS[r0 + 8];
#pragma unroll
        for (int ni = 0; ni < 4; ni++) {
            int col = n0 + nw * 32 + ni * 8 + 2 * tq;
            if (t0 >= 0)
                *(float2*)(out + (size_t)t0 * HIDDEN + col) =
                    make_float2(acc[mi][ni][0], acc[mi][ni][1]);
            if (t1 >= 0)
                *(float2*)(out + (size_t)t1 * HIDDEN + col) =
                    make_float2(acc[mi][ni][2], acc[mi][ni][3]);
        }
    }
}

// ---------------- launch ----------------
extern "C" void kernel_launch(void* const* d_in, const int* in_sizes, int n_in,
                              void* d_out, int out_size) {
    const float* x    = (const float*)d_in[0];
    const int*   tids = (const int*)d_in[1];
    const float* gup  = (const float*)d_in[2];
    const float* down = (const float*)d_in[3];
    float*       out  = (float*)d_out;

    cudaFuncSetAttribute(pack_x_kernel, cudaFuncAttributeMaxDynamicSharedMemorySize, PX_SMEM);

    detect_kernel<<<1, 32>>>(tids);
    route_kernel<<<NUM_TOKENS / 256, 256>>>(tids);

    pack_x_kernel<<<dim3(HIDDEN / 128, MAX_TILES), 256, PX_SMEM>>>(x);
    gemm1_tc<<<dim3(MAX_TILES, INTER / 64), 256>>>(gup);
    gemm2_tc<<<dim3(MAX_TILES, HIDDEN / 128), 256>>>(down, out);
}